// round 5
// baseline (speedup 1.0000x reference)
#include <cuda_runtime.h>
#include <cuda_bf16.h>
#include <cstdint>

// InverseAvgPool1d, K=8 -> half=4, s=9.
// out[t] = 8*(A[t] - A[t-1]) + 8*x0*( [t%9==5] - [t%9==0] ),
// where A[t] = stride-9 prefix sum of x along the row, A[-1]=0.
//
// Each CTA handles ROWS_PER_CTA rows, double-buffered smem; next row
// prefetched via cp.async.bulk (TMA) overlapping current compute.

#define ROW_T 4096
#define ROW_BYTES 16384
#define NWARP 9
#define NTHREADS (NWARP * 32)   // 288
#define PER_LANE 15             // 32*15 = 480 slots; real max 456
#define ROWS_PER_CTA 16

__global__ __launch_bounds__(NTHREADS)
void inv_avgpool_kernel(const float* __restrict__ x, float* __restrict__ out) {
    __shared__ __align__(16) float sbuf[2][ROW_T];
    __shared__ __align__(8) unsigned long long mbar[2];

    const int tid = threadIdx.x;
    const int lane = tid & 31;
    const int r = tid >> 5;                  // residue chain 0..8

    const uint32_t mb0 = (uint32_t)__cvta_generic_to_shared(&mbar[0]);
    const uint32_t mb1 = (uint32_t)__cvta_generic_to_shared(&mbar[1]);
    const uint32_t sb0 = (uint32_t)__cvta_generic_to_shared(&sbuf[0][0]);
    const uint32_t sb1 = (uint32_t)__cvta_generic_to_shared(&sbuf[1][0]);

    const size_t row0 = (size_t)blockIdx.x * ROWS_PER_CTA;

    if (tid == 0) {
        asm volatile("mbarrier.init.shared.b64 [%0], 1;" :: "r"(mb0) : "memory");
        asm volatile("mbarrier.init.shared.b64 [%0], 1;" :: "r"(mb1) : "memory");
        asm volatile("fence.proxy.async.shared::cta;" ::: "memory");
    }
    __syncthreads();
    if (tid == 0) {   // prologue: fetch row 0 into buffer 0
        asm volatile("mbarrier.arrive.expect_tx.shared.b64 _, [%0], %1;"
                     :: "r"(mb0), "r"(ROW_BYTES) : "memory");
        asm volatile("cp.async.bulk.shared::cta.global.mbarrier::complete_tx::bytes "
                     "[%0], [%1], %2, [%3];"
                     :: "r"(sb0), "l"(x + row0 * ROW_T), "r"(ROW_BYTES), "r"(mb0)
                     : "memory");
    }

    const int n = (r == 0) ? 456 : 455;      // chain length
    const int base = r + 135 * lane;         // lanes 0..29: base+126 <= 4049 (in-bounds)
    const int lim30 = n - 450;               // valid count for lane 30 (5 or 6)

    // residue-correction coefficients for the diff pass (per thread, static)
    const int rr0 = (4 * tid) % 9;
    const int rr1 = (rr0 + 1) % 9, rr2 = (rr0 + 2) % 9, rr3 = (rr0 + 3) % 9;
    const float cfx = (rr0 == 5) ? 8.f : (rr0 == 0) ? -8.f : 0.f;
    const float cfy = (rr1 == 5) ? 8.f : (rr1 == 0) ? -8.f : 0.f;
    const float cfz = (rr2 == 5) ? 8.f : (rr2 == 0) ? -8.f : 0.f;
    const float cfw = (rr3 == 5) ? 8.f : (rr3 == 0) ? -8.f : 0.f;

    for (int k = 0; k < ROWS_PER_CTA; k++) {
        const int cur = k & 1;
        const uint32_t mbc = cur ? mb1 : mb0;
        float* s = sbuf[cur];

        __syncthreads();   // close previous iteration's accesses to both buffers

        if (tid == 0 && k + 1 < ROWS_PER_CTA) {
            asm volatile("fence.proxy.async.shared::cta;" ::: "memory");
            const uint32_t mbn = cur ? mb0 : mb1;
            const uint32_t sbn = cur ? sb0 : sb1;
            asm volatile("mbarrier.arrive.expect_tx.shared.b64 _, [%0], %1;"
                         :: "r"(mbn), "r"(ROW_BYTES) : "memory");
            asm volatile("cp.async.bulk.shared::cta.global.mbarrier::complete_tx::bytes "
                         "[%0], [%1], %2, [%3];"
                         :: "r"(sbn), "l"(x + (row0 + k + 1) * ROW_T), "r"(ROW_BYTES),
                            "r"(mbn)
                         : "memory");
        }

        // wait for current buffer (parity flips every 2 iterations per buffer)
        const unsigned int ph = (k >> 1) & 1;
        asm volatile(
            "{\n\t.reg .pred P;\n\t"
            "LAB_W%=:\n\t"
            "mbarrier.try_wait.parity.acquire.cta.shared::cta.b64 P, [%0], %1, 0x989680;\n\t"
            "@P bra.uni LAB_D%=;\n\t"
            "bra.uni LAB_W%=;\n\t"
            "LAB_D%=:\n\t}"
            :: "r"(mbc), "r"(ph) : "memory");

        const float x0 = s[0];

        // gather: lane l serially accumulates chain slots [15l,15l+15)
        float a[PER_LANE];
        float run = 0.f;
        if (lane < 30) {
            #pragma unroll
            for (int j = 0; j < PER_LANE; j++) { run += s[base + 9 * j]; a[j] = run; }
        } else if (lane == 30) {
            #pragma unroll
            for (int j = 0; j < PER_LANE; j++) {
                if (j < lim30) run += s[base + 9 * j];
                a[j] = run;
            }
        }
        __syncthreads();

        // warp scan over lane totals -> exclusive carry
        float incl = run;
        #pragma unroll
        for (int off = 1; off < 32; off <<= 1) {
            float up = __shfl_up_sync(0xffffffffu, incl, off);
            if (lane >= off) incl += up;
        }
        const float e8 = 8.f * (incl - run);

        // writeback 8*A
        if (lane < 30) {
            #pragma unroll
            for (int j = 0; j < PER_LANE; j++) s[base + 9 * j] = fmaf(8.f, a[j], e8);
        } else if (lane == 30) {
            #pragma unroll
            for (int j = 0; j < PER_LANE; j++)
                if (j < lim30) s[base + 9 * j] = fmaf(8.f, a[j], e8);
        }
        __syncthreads();

        // diff pass: out[t] = 8A[t]-8A[t-1] + cf*x0
        float4* __restrict__ outr = (float4*)(out + (row0 + k) * ROW_T);
        #pragma unroll
        for (int q = tid; q < ROW_T / 4; q += NTHREADS) {
            float4 B = ((const float4*)s)[q];
            float prevw = __shfl_up_sync(0xffffffffu, B.w, 1);
            if (lane == 0) prevw = (q == 0) ? 0.f : s[4 * q - 1];
            float4 o;
            o.x = (B.x - prevw) + cfx * x0;
            o.y = (B.y - B.x) + cfy * x0;
            o.z = (B.z - B.y) + cfz * x0;
            o.w = (B.w - B.z) + cfw * x0;
            outr[q] = o;
        }
    }
}

extern "C" void kernel_launch(void* const* d_in, const int* in_sizes, int n_in,
                              void* d_out, int out_size) {
    const float* x = (const float*)d_in[0];
    float* out = (float*)d_out;
    const int rows = in_sizes[0] / ROW_T;       // 16384
    const int grid = rows / ROWS_PER_CTA;       // 1024
    inv_avgpool_kernel<<<grid, NTHREADS>>>(x, out);
}